// round 7
// baseline (speedup 1.0000x reference)
#include <cuda_runtime.h>
#include <math.h>

// Problem constants (fixed by the reference)
#define TOK_TOTAL 16384          // B*L = 4*4096
#define DDIM      2048
#define NEXP      64
#define BLK_M     64             // tokens per block
#define NBLK      (TOK_TOTAL / BLK_M)   // 256
#define KC        32             // k-chunk per smem stage
#define NCHUNK    (DDIM / KC)    // 64
#define NTHREADS  128            // 16 expert-groups x 8 token-pair-groups
#define XP        34             // x smem pitch (ull per token-pair row), padded
#define WP        66             // w smem pitch (ull per k row), padded

// Per-block partials for the aux loss (written fully every launch -> deterministic)
__device__ float g_pprob[NBLK * NEXP];
__device__ float g_pcnt [NBLK * NEXP];

__device__ __forceinline__ unsigned long long dup_f32(float v) {
    unsigned int u = __float_as_uint(v);
    return ((unsigned long long)u << 32) | (unsigned long long)u;
}

// Packed dual fp32 FMA: c.lo += a.lo*b.lo ; c.hi += a.hi*b.hi   (SASS: FFMA2)
#define FMA2(c, a, b) asm("fma.rn.f32x2 %0, %1, %2, %0;" : "+l"(c) : "l"(a), "l"(b))

__global__ void __launch_bounds__(NTHREADS)
router_gemm_kernel(const float* __restrict__ x, const float* __restrict__ W,
                   float* __restrict__ out)
{
    // GEMM staging buffers and epilogue buffers alias (never live simultaneously)
    __shared__ union {
        struct {
            unsigned long long xs[32 * XP];   // [token-pair][k] : {x[2p][k], x[2p+1][k]}
            unsigned long long ws[KC * WP];   // [k][expert]     : {w, w} duplicated
        } g;
        struct {
            float logits[BLK_M * 65];         // [token][expert], pitch 65
            float m1[BLK_M];
            float rs[BLK_M];
            int   i1[BLK_M];
        } e;
    } sm;

    const int tid = threadIdx.x;
    const int tx  = tid & 15;     // expert group: experts tx, tx+16, tx+32, tx+48
    const int ty  = tid >> 4;     // token-pair group (0..7): pairs ty, ty+8, ty+16, ty+24
    const int blk = blockIdx.x;

    const float* xblk = x + (size_t)blk * BLK_M * DDIM;

    unsigned long long acc[4][4];
#pragma unroll
    for (int i = 0; i < 4; i++)
#pragma unroll
        for (int j = 0; j < 4; j++) acc[i][j] = 0ull;

    // ---- per-thread constant addressing for global loads / smem stores ----
    const float* xg[4];
    const float* wg[4];
    int xsb[4], wsb[4];
#pragma unroll
    for (int r = 0; r < 4; r++) {
        int f   = r * NTHREADS + tid;   // 0..511 over the 64x32-float tile
        int row = f >> 3;               // token (or expert) row 0..63
        int kq  = f & 7;                // float4 column 0..7
        xg[r]  = xblk + row * DDIM + kq * 4;
        wg[r]  = W    + row * DDIM + kq * 4;
        xsb[r] = ((row >> 1) * XP + kq * 4) * 2 + (row & 1);  // float index in xs
        wsb[r] = (kq * 4) * WP + row;                          // ull index in ws
    }

    float4 xf[4], wf[4];
#pragma unroll
    for (int r = 0; r < 4; r++) {       // prefetch chunk 0
        xf[r] = *(const float4*)xg[r];
        wf[r] = *(const float4*)wg[r];
    }

    float* xs_f = (float*)sm.g.xs;

    for (int c = 0; c < NCHUNK; c++) {
        // stage prefetched chunk into smem (x interleaved by token parity, W duplicated)
#pragma unroll
        for (int r = 0; r < 4; r++) {
            xs_f[xsb[r] + 0] = xf[r].x;
            xs_f[xsb[r] + 2] = xf[r].y;
            xs_f[xsb[r] + 4] = xf[r].z;
            xs_f[xsb[r] + 6] = xf[r].w;
            sm.g.ws[wsb[r] + 0 * WP] = dup_f32(wf[r].x);
            sm.g.ws[wsb[r] + 1 * WP] = dup_f32(wf[r].y);
            sm.g.ws[wsb[r] + 2 * WP] = dup_f32(wf[r].z);
            sm.g.ws[wsb[r] + 3 * WP] = dup_f32(wf[r].w);
        }
        __syncthreads();

        // prefetch next chunk while computing this one
        if (c + 1 < NCHUNK) {
            int off = (c + 1) * KC;
#pragma unroll
            for (int r = 0; r < 4; r++) {
                xf[r] = *(const float4*)(xg[r] + off);
                wf[r] = *(const float4*)(wg[r] + off);
            }
        }

        // main compute: per 2 k-steps -> 32 FFMA2 + 12 LDS
#pragma unroll
        for (int k = 0; k < KC; k += 2) {
            ulonglong2 xv[4];
#pragma unroll
            for (int i = 0; i < 4; i++)
                xv[i] = *(const ulonglong2*)&sm.g.xs[(ty + 8 * i) * XP + k];
            unsigned long long w0[4], w1[4];
#pragma unroll
            for (int j = 0; j < 4; j++) {
                w0[j] = sm.g.ws[ k      * WP + tx + 16 * j];
                w1[j] = sm.g.ws[(k + 1) * WP + tx + 16 * j];
            }
#pragma unroll
            for (int i = 0; i < 4; i++)
#pragma unroll
                for (int j = 0; j < 4; j++) {
                    FMA2(acc[i][j], xv[i].x, w0[j]);
                    FMA2(acc[i][j], xv[i].y, w1[j]);
                }
        }
        __syncthreads();
    }

    // ---- epilogue: spill logits to smem (aliases GEMM buffers, all reads done) ----
    float* L = sm.e.logits;
#pragma unroll
    for (int i = 0; i < 4; i++) {
        int p = ty + 8 * i;
#pragma unroll
        for (int j = 0; j < 4; j++) {
            int e = tx + 16 * j;
            unsigned long long u = acc[i][j];
            L[(2 * p)     * 65 + e] = __uint_as_float((unsigned int)u);
            L[(2 * p + 1) * 65 + e] = __uint_as_float((unsigned int)(u >> 32));
        }
    }
    __syncthreads();

    // one thread per token: top-2 (stable, lowest-index on ties, like lax.top_k),
    // softmax normalizer, and the index/weight outputs
    if (tid < BLK_M) {
        const float* row = L + tid * 65;
        float m1 = -3.402823466e38f, m2 = -3.402823466e38f;
        int i1 = 0, i2 = 0;
#pragma unroll
        for (int e = 0; e < NEXP; e++) {
            float v = row[e];
            if (v > m1)      { m2 = m1; i2 = i1; m1 = v; i1 = e; }
            else if (v > m2) { m2 = v; i2 = e; }
        }
        float s = 0.0f;
#pragma unroll
        for (int e = 0; e < NEXP; e++) s += expf(row[e] - m1);

        sm.e.m1[tid] = m1;
        sm.e.rs[tid] = 1.0f / s;
        sm.e.i1[tid] = i1;

        int g = blk * BLK_M + tid;
        float q   = expf(m2 - m1);
        float inv = 1.0f / (1.0f + q);
        out[2 * g]                     = (float)i1;   // top_k_indices (as float)
        out[2 * g + 1]                 = (float)i2;
        out[2 * TOK_TOTAL + 2 * g]     = inv;         // top_k_weights
        out[2 * TOK_TOTAL + 2 * g + 1] = q * inv;
    }
    __syncthreads();

    // one thread per expert: deterministic per-block prob-sum / top-1 count
    if (tid < NEXP) {
        float ps = 0.0f, cs = 0.0f;
#pragma unroll 8
        for (int t = 0; t < BLK_M; t++) {
            float l = L[t * 65 + tid];
            ps += expf(l - sm.e.m1[t]) * sm.e.rs[t];
            cs += (sm.e.i1[t] == tid) ? 1.0f : 0.0f;
        }
        g_pprob[blk * NEXP + tid] = ps;
        g_pcnt [blk * NEXP + tid] = cs;
    }
}

// Fold the 256 block-partials into the aux-loss scalar (deterministic order)
__global__ void router_aux_kernel(float* __restrict__ out)
{
    __shared__ float sP[4][NEXP];
    __shared__ float sC[4][NEXP];
    __shared__ float red[NEXP];
    int tid  = threadIdx.x;      // 256
    int e    = tid & 63;
    int part = tid >> 6;         // 4 parts x 64 blocks
    float sp = 0.0f, sc = 0.0f;
    int b0 = part * (NBLK / 4);
#pragma unroll 8
    for (int b = b0; b < b0 + NBLK / 4; b++) {
        sp += g_pprob[b * NEXP + e];
        sc += g_pcnt [b * NEXP + e];
    }
    sP[part][e] = sp;
    sC[part][e] = sc;
    __syncthreads();
    if (tid < NEXP) {
        float P = sP[0][e] + sP[1][e] + sP[2][e] + sP[3][e];
        float C = sC[0][e] + sC[1][e] + sC[2][e] + sC[3][e];
        red[e] = (C * (1.0f / TOK_TOTAL)) * (P * (1.0f / TOK_TOTAL));
    }
    __syncthreads();
    if (tid == 0) {
        float s = 0.0f;
        for (int k = 0; k < NEXP; k++) s += red[k];
        out[4 * TOK_TOTAL] = (float)NEXP * s * 0.01f;   // E * sum * aux_w
    }
}

extern "C" void kernel_launch(void* const* d_in, const int* in_sizes, int n_in,
                              void* d_out, int out_size)
{
    const float* x = (const float*)d_in[0];
    const float* W = (const float*)d_in[1];
    // defensive: identify inputs by size if order ever differs
    if (n_in >= 2 && in_sizes[0] == NEXP * DDIM && in_sizes[1] == TOK_TOTAL * DDIM) {
        const float* t = x; x = W; W = t;
    }
    float* out = (float*)d_out;
    router_gemm_kernel<<<NBLK, NTHREADS>>>(x, W, out);
    router_aux_kernel<<<1, 256>>>(out);
}

// round 9
// speedup vs baseline: 1.2477x; 1.2477x over previous
#include <cuda_runtime.h>
#include <math.h>

// Problem constants
#define TOK   16384            // B*L
#define DDIM  2048
#define NEXP  64
#define BLK_M 128              // tokens per block
#define NBLK  (TOK / BLK_M)    // 128 blocks = one wave on 148 SMs
#define KC    16               // k floats per smem stage
#define NCH   (DDIM / KC)      // 128 chunks
#define NT    128              // threads per block
#define PU    10               // ull pitch per row (8 data + 2 pad) -> conflict-free LDS.64

// Per-block aux partials + arrival counter (last block folds them; resets counter)
__device__ float g_pprob[NBLK * NEXP];
__device__ float g_pcnt [NBLK * NEXP];
__device__ unsigned int g_arrival = 0;

// Packed dual fp32 FMA: c.lo += a.lo*b.lo ; c.hi += a.hi*b.hi
#define FMA2(c, a, b) asm("fma.rn.f32x2 %0, %1, %2, %0;" : "+l"(c) : "l"(a), "l"(b))
#define CP16(dst, src) \
    asm volatile("cp.async.cg.shared.global [%0], [%1], 16;" :: "r"(dst), "l"(src))
#define CPCOMMIT() asm volatile("cp.async.commit_group;")
#define CPWAIT1()  asm volatile("cp.async.wait_group 1;")

struct Stage {
    unsigned long long xs[BLK_M * PU];  // [token][k-pair], natural gmem packing
    unsigned long long ws[NEXP  * PU];  // [expert][k-pair]
};

__global__ void __launch_bounds__(NT, 1)
router_kernel(const float* __restrict__ x, const float* __restrict__ W,
              float* __restrict__ out)
{
    __shared__ __align__(16) union {
        Stage st[2];
        struct {
            float L[BLK_M * 65];        // logits, pitch 65
            float m1[BLK_M], rs[BLK_M];
            int   i1[BLK_M];
            int   flag;
            float rP[2][NEXP], rC[2][NEXP], red[NEXP];
        } e;
    } sm;

    const int tid = threadIdx.x;
    const int tx  = tid & 7;     // expert group: experts tx + 8j, j=0..7
    const int ty  = tid >> 3;    // token group:  tokens  ty + 16i, i=0..7
    const int blk = blockIdx.x;

    // ---- staging addresses: 6 x 16B cp.async per thread per chunk ----
    const int srow = tid >> 2;   // 0..31
    const int skk  = tid & 3;    // which 16B (= 2 k-pairs) within the KC window
    const float* xg[4];
    const float* wg[2];
    unsigned xd[2][4], wd[2][2];
#pragma unroll
    for (int r = 0; r < 4; r++) {
        int t = r * 32 + srow;
        xg[r] = x + (size_t)blk * BLK_M * DDIM + (size_t)t * DDIM + skk * 4;
        xd[0][r] = (unsigned)__cvta_generic_to_shared(&sm.st[0].xs[t * PU + skk * 2]);
        xd[1][r] = (unsigned)__cvta_generic_to_shared(&sm.st[1].xs[t * PU + skk * 2]);
    }
#pragma unroll
    for (int r = 0; r < 2; r++) {
        int e = r * 32 + srow;
        wg[r] = W + (size_t)e * DDIM + skk * 4;
        wd[0][r] = (unsigned)__cvta_generic_to_shared(&sm.st[0].ws[e * PU + skk * 2]);
        wd[1][r] = (unsigned)__cvta_generic_to_shared(&sm.st[1].ws[e * PU + skk * 2]);
    }

    unsigned long long acc[8][8];
#pragma unroll
    for (int i = 0; i < 8; i++)
#pragma unroll
        for (int j = 0; j < 8; j++) acc[i][j] = 0ull;

    // prefetch chunk 0
    {
#pragma unroll
        for (int r = 0; r < 4; r++) CP16(xd[0][r], xg[r]);
#pragma unroll
        for (int r = 0; r < 2; r++) CP16(wd[0][r], wg[r]);
        CPCOMMIT();
    }

    for (int c = 0; c < NCH; c++) {
        // issue next chunk into the other stage (stage was freed by bar at end of c-1)
        if (c + 1 < NCH) {
            int s = (c + 1) & 1, off = (c + 1) * KC;
#pragma unroll
            for (int r = 0; r < 4; r++) CP16(xd[s][r], xg[r] + off);
#pragma unroll
            for (int r = 0; r < 2; r++) CP16(wd[s][r], wg[r] + off);
        }
        CPCOMMIT();      // empty group on last iter keeps wait accounting uniform
        CPWAIT1();       // chunk c's copies done
        __syncthreads();

        const unsigned long long* xb = sm.st[c & 1].xs + ty * PU;
        const unsigned long long* wb = sm.st[c & 1].ws + tx * PU;
#pragma unroll
        for (int kk = 0; kk < KC / 2; kk++) {
            unsigned long long xv[8], wv[8];
#pragma unroll
            for (int i = 0; i < 8; i++) xv[i] = xb[160 * i + kk];  // (ty+16i)*PU
#pragma unroll
            for (int j = 0; j < 8; j++) wv[j] = wb[ 80 * j + kk];  // (tx+8j)*PU
#pragma unroll
            for (int i = 0; i < 8; i++)
#pragma unroll
                for (int j = 0; j < 8; j++) FMA2(acc[i][j], xv[i], wv[j]);
        }
        __syncthreads();  // protect stage c&1 from the overwrite at iter c+1
    }

    // ---- epilogue: fold k-split lanes, spill logits (aliases stage smem) ----
    float* L = sm.e.L;
#pragma unroll
    for (int i = 0; i < 8; i++) {
        int t = ty + 16 * i;
#pragma unroll
        for (int j = 0; j < 8; j++) {
            unsigned long long u = acc[i][j];
            float lo = __uint_as_float((unsigned)u);
            float hi = __uint_as_float((unsigned)(u >> 32));
            L[t * 65 + (tx + 8 * j)] = lo + hi;
        }
    }
    __syncthreads();

    // one thread per token: top-2 (strict >, lowest index on ties, like lax.top_k)
    {
        const float* row = L + tid * 65;
        float m1 = -3.402823466e38f, m2 = -3.402823466e38f;
        int i1 = 0, i2 = 0;
#pragma unroll
        for (int e = 0; e < NEXP; e++) {
            float v = row[e];
            if (v > m1)      { m2 = m1; i2 = i1; m1 = v; i1 = e; }
            else if (v > m2) { m2 = v; i2 = e; }
        }
        float s = 0.0f;
#pragma unroll
        for (int e = 0; e < NEXP; e++) s += expf(row[e] - m1);

        sm.e.m1[tid] = m1;
        sm.e.rs[tid] = 1.0f / s;
        sm.e.i1[tid] = i1;

        int g = blk * BLK_M + tid;
        float q   = expf(m2 - m1);
        float inv = 1.0f / (1.0f + q);
        out[2 * g]               = (float)i1;   // top_k_indices
        out[2 * g + 1]           = (float)i2;
        out[2 * TOK + 2 * g]     = inv;         // top_k_weights
        out[2 * TOK + 2 * g + 1] = q * inv;
    }
    __syncthreads();

    // one thread per expert: deterministic per-block prob-sum / top-1 count
    if (tid < NEXP) {
        float ps = 0.0f, cs = 0.0f;
#pragma unroll 8
        for (int t = 0; t < BLK_M; t++) {
            float l = L[t * 65 + tid];
            ps += expf(l - sm.e.m1[t]) * sm.e.rs[t];
            cs += (sm.e.i1[t] == tid) ? 1.0f : 0.0f;
        }
        g_pprob[blk * NEXP + tid] = ps;
        g_pcnt [blk * NEXP + tid] = cs;
    }
    __syncthreads();

    // ---- fused aux loss: last-arriving block folds all partials ----
    if (tid == 0) {
        __threadfence();
        unsigned old = atomicAdd(&g_arrival, 1u);
        sm.e.flag = (old == NBLK - 1) ? 1 : 0;
    }
    __syncthreads();
    if (sm.e.flag) {
        __threadfence();  // acquire side: make all blocks' partials visible
        int e = tid & 63, h = tid >> 6;             // 2 halves x 64 blocks
        float sp = 0.0f, sc = 0.0f;
        int b0 = h * (NBLK / 2);
#pragma unroll 8
        for (int b = b0; b < b0 + NBLK / 2; b++) {
            sp += g_pprob[b * NEXP + e];
            sc += g_pcnt [b * NEXP + e];
        }
        sm.e.rP[h][e] = sp;
        sm.e.rC[h][e] = sc;
        __syncthreads();
        if (tid < NEXP) {
            float P = sm.e.rP[0][tid] + sm.e.rP[1][tid];
            float C = sm.e.rC[0][tid] + sm.e.rC[1][tid];
            sm.e.red[tid] = (C * (1.0f / TOK)) * (P * (1.0f / TOK));
        }
        __syncthreads();
        if (tid == 0) {
            float s = 0.0f;
            for (int k = 0; k < NEXP; k++) s += sm.e.red[k];
            out[4 * TOK] = (float)NEXP * s * 0.01f;  // E * sum * aux_w
            g_arrival = 0;                            // reset for next graph replay
        }
    }
}

extern "C" void kernel_launch(void* const* d_in, const int* in_sizes, int n_in,
                              void* d_out, int out_size)
{
    const float* x = (const float*)d_in[0];
    const float* W = (const float*)d_in[1];
    if (n_in >= 2 && in_sizes[0] == NEXP * DDIM && in_sizes[1] == TOK * DDIM) {
        const float* t = x; x = W; W = t;
    }
    router_kernel<<<NBLK, NT>>>(x, W, (float*)d_out);
}

// round 10
// speedup vs baseline: 1.3254x; 1.0623x over previous
#include <cuda_runtime.h>
#include <math.h>

// Problem constants
#define TOK   16384            // B*L
#define DDIM  2048
#define NEXP  64
#define BLK_M 128              // tokens per block
#define NBLK  (TOK / BLK_M)    // 128 blocks = one wave
#define KC    16               // k floats per stage
#define NCH   (DDIM / KC)      // 128 chunks
#define NT    256              // 8 warps = 2 per SMSP
#define PU    10               // ull pitch per row (8 data + 2 pad)
#define NSTG  3                // cp.async ring depth
#define XS_ULL (BLK_M * PU)    // 1280
#define STG_ULL (XS_ULL + NEXP * PU)   // 1920 (15360 B per stage)

// Per-block aux partials + arrival counter (fused last-block reduction)
__device__ float g_pprob[NBLK * NEXP];
__device__ float g_pcnt [NBLK * NEXP];
__device__ unsigned int g_arrival = 0;

// Packed dual fp32 FMA: c.lo += a.lo*b.lo ; c.hi += a.hi*b.hi
#define FMA2(c, a, b) asm("fma.rn.f32x2 %0, %1, %2, %0;" : "+l"(c) : "l"(a), "l"(b))
#define CP16(dst, src) \
    asm volatile("cp.async.cg.shared.global [%0], [%1], 16;" :: "r"(dst), "l"(src))
#define CPCOMMIT() asm volatile("cp.async.commit_group;")
#define CPWAIT1()  asm volatile("cp.async.wait_group 1;")

__global__ void __launch_bounds__(NT, 1)
router_kernel(const float* __restrict__ x, const float* __restrict__ W,
              float* __restrict__ out)
{
    __shared__ __align__(16) union {
        unsigned long long st[NSTG * STG_ULL];     // 46080 B
        struct {
            float L[BLK_M * 65];                   // logits, pitch 65
            float m1[BLK_M], rs[BLK_M];
            int   i1[BLK_M];
            int   flag;
            float rP[4][NEXP], rC[4][NEXP], red[NEXP];
        } e;
    } sm;

    const int tid = threadIdx.x;
    const int tx  = tid & 7;     // experts tx + 8j, j=0..7
    const int ty  = tid >> 3;    // tokens  ty + 32i, i=0..3 (ty 0..31)
    const int blk = blockIdx.x;

    // ---- staging map: 3 x 16B cp.async per thread per chunk ----
    const float* sg[3];
    unsigned sd[3];              // dst smem addr in stage 0
#pragma unroll
    for (int q = 0; q < 3; q++) {
        int f = q * NT + tid;    // 0..767
        int dstull; const float* base;
        if (f < 512) {           // x: 128 rows x 4 x 16B
            int row = f >> 2, kq = f & 3;
            base   = x + (size_t)blk * BLK_M * DDIM + (size_t)row * DDIM + kq * 4;
            dstull = row * PU + kq * 2;
        } else {                 // W: 64 rows x 4 x 16B
            int g = f - 512, row = g >> 2, kq = g & 3;
            base   = W + (size_t)row * DDIM + kq * 4;
            dstull = XS_ULL + row * PU + kq * 2;
        }
        sg[q] = base;
        sd[q] = (unsigned)__cvta_generic_to_shared(&sm.st[dstull]);
    }

    unsigned long long acc[4][8];
#pragma unroll
    for (int i = 0; i < 4; i++)
#pragma unroll
        for (int j = 0; j < 8; j++) acc[i][j] = 0ull;

    // prologue: prefetch chunks 0 and 1
#pragma unroll
    for (int s = 0; s < 2; s++) {
#pragma unroll
        for (int q = 0; q < 3; q++) CP16(sd[q] + s * (STG_ULL * 8), sg[q] + s * KC);
        CPCOMMIT();
    }

    int cs = 0, ps = 2;          // compute slot, prefetch slot
    for (int c = 0; c < NCH; c++) {
        CPWAIT1();               // oldest outstanding group (chunk c) landed
        __syncthreads();         // ...and visible to all threads

        if (c + 2 < NCH) {       // issue chunk c+2 into slot ps (safe: != cs, != cs+1)
            int off = (c + 2) * KC;
#pragma unroll
            for (int q = 0; q < 3; q++) CP16(sd[q] + ps * (STG_ULL * 8), sg[q] + off);
        }
        CPCOMMIT();              // (possibly empty) keeps wait accounting uniform

        const unsigned long long* xb = sm.st + cs * STG_ULL + ty * PU;
        const unsigned long long* wb = sm.st + cs * STG_ULL + XS_ULL + tx * PU;
#pragma unroll
        for (int kk = 0; kk < KC / 2; kk++) {
            unsigned long long xv[4], wv[8];
#pragma unroll
            for (int i = 0; i < 4; i++) xv[i] = xb[320 * i + kk];  // (ty+32i)*PU
#pragma unroll
            for (int j = 0; j < 8; j++) wv[j] = wb[ 80 * j + kk];  // (tx+8j)*PU
#pragma unroll
            for (int i = 0; i < 4; i++)
#pragma unroll
                for (int j = 0; j < 8; j++) FMA2(acc[i][j], xv[i], wv[j]);
        }
        cs = (cs == NSTG - 1) ? 0 : cs + 1;
        ps = (ps == NSTG - 1) ? 0 : ps + 1;
    }
    __syncthreads();             // all reads of st done before epilogue overlays it

    // ---- epilogue: fold k-split lanes, spill logits ----
    float* L = sm.e.L;
#pragma unroll
    for (int i = 0; i < 4; i++) {
        int t = ty + 32 * i;
#pragma unroll
        for (int j = 0; j < 8; j++) {
            unsigned long long u = acc[i][j];
            L[t * 65 + (tx + 8 * j)] =
                __uint_as_float((unsigned)u) + __uint_as_float((unsigned)(u >> 32));
        }
    }
    __syncthreads();

    // one thread per token: top-2 (strict >, lowest index on ties, like lax.top_k)
    if (tid < BLK_M) {
        const float* row = L + tid * 65;
        float m1 = -3.402823466e38f, m2 = -3.402823466e38f;
        int i1 = 0, i2 = 0;
#pragma unroll
        for (int e = 0; e < NEXP; e++) {
            float v = row[e];
            if (v > m1)      { m2 = m1; i2 = i1; m1 = v; i1 = e; }
            else if (v > m2) { m2 = v; i2 = e; }
        }
        float s = 0.0f;
#pragma unroll
        for (int e = 0; e < NEXP; e++) s += __expf(row[e] - m1);

        sm.e.m1[tid] = m1;
        sm.e.rs[tid] = 1.0f / s;
        sm.e.i1[tid] = i1;

        int g = blk * BLK_M + tid;
        float q   = __expf(m2 - m1);
        float inv = 1.0f / (1.0f + q);
        out[2 * g]               = (float)i1;   // top_k_indices
        out[2 * g + 1]           = (float)i2;
        out[2 * TOK + 2 * g]     = inv;         // top_k_weights
        out[2 * TOK + 2 * g + 1] = q * inv;
    }
    __syncthreads();

    // one thread per expert: deterministic per-block prob-sum / top-1 count
    if (tid < NEXP) {
        float ps2 = 0.0f, cs2 = 0.0f;
#pragma unroll 8
        for (int t = 0; t < BLK_M; t++) {
            ps2 += __expf(L[t * 65 + tid] - sm.e.m1[t]) * sm.e.rs[t];
            cs2 += (sm.e.i1[t] == tid) ? 1.0f : 0.0f;
        }
        g_pprob[blk * NEXP + tid] = ps2;
        g_pcnt [blk * NEXP + tid] = cs2;
    }
    __syncthreads();

    // ---- fused aux loss: last-arriving block folds all partials ----
    if (tid == 0) {
        __threadfence();
        unsigned old = atomicAdd(&g_arrival, 1u);
        sm.e.flag = (old == NBLK - 1) ? 1 : 0;
    }
    __syncthreads();
    if (sm.e.flag) {
        __threadfence();
        int e = tid & 63, h = tid >> 6;          // 4 parts x 32 blocks
        float sp = 0.0f, sc = 0.0f;
        int b0 = h * (NBLK / 4);
#pragma unroll 8
        for (int b = b0; b < b0 + NBLK / 4; b++) {
            sp += g_pprob[b * NEXP + e];
            sc += g_pcnt [b * NEXP + e];
        }
        sm.e.rP[h][e] = sp;
        sm.e.rC[h][e] = sc;
        __syncthreads();
        if (tid < NEXP) {
            float P = sm.e.rP[0][tid] + sm.e.rP[1][tid] + sm.e.rP[2][tid] + sm.e.rP[3][tid];
            float C = sm.e.rC[0][tid] + sm.e.rC[1][tid] + sm.e.rC[2][tid] + sm.e.rC[3][tid];
            sm.e.red[tid] = (C * (1.0f / TOK)) * (P * (1.0f / TOK));
        }
        __syncthreads();
        if (tid == 0) {
            float s = 0.0f;
            for (int k = 0; k < NEXP; k++) s += sm.e.red[k];
            out[4 * TOK] = (float)NEXP * s * 0.01f;  // E * sum * aux_w
            g_arrival = 0;                            // reset for next graph replay
        }
    }
}

extern "C" void kernel_launch(void* const* d_in, const int* in_sizes, int n_in,
                              void* d_out, int out_size)
{
    const float* x = (const float*)d_in[0];
    const float* W = (const float*)d_in[1];
    if (n_in >= 2 && in_sizes[0] == NEXP * DDIM && in_sizes[1] == TOK * DDIM) {
        const float* t = x; x = W; W = t;
    }
    router_kernel<<<NBLK, NT>>>(x, W, (float*)d_out);
}

// round 13
// speedup vs baseline: 1.7252x; 1.3017x over previous
#include <cuda_runtime.h>
#include <cstdint>
#include <math.h>

// ---------------- problem constants ----------------
#define TOK    16384
#define DDIM   2048
#define NEXP   64
#define BLK_M  128
#define NBLK   (TOK / BLK_M)     // 128 blocks = one wave
#define KCH    32                // k floats per chunk
#define NCH    (DDIM / KCH)      // 64 chunks
#define NT     256

// smem staging (floats), pitch 36 = 32 data + 4 pad -> conflict-free frags
#define PITCH  36
#define A_HI   0
#define A_LO   (BLK_M * PITCH)                 // 4608
#define B_HI   (2 * BLK_M * PITCH)             // 9216
#define B_LO   (B_HI + NEXP * PITCH)           // 11520
#define STG_F  (B_LO + NEXP * PITCH)           // 13824 floats = 55296 B
#define SMEM_TOTAL (2 * STG_F * 4)             // 110592 B

// aux-loss partials + arrival counter (fused last-block reduction)
__device__ float g_pprob[NBLK * NEXP];
__device__ float g_pcnt [NBLK * NEXP];
__device__ unsigned int g_arrival = 0;

__device__ __forceinline__ float tf32_rn(float v) {
    uint32_t u; asm("cvt.rna.tf32.f32 %0, %1;" : "=r"(u) : "f"(v));
    return __uint_as_float(u);
}

// m16n8k8 tf32 MMA, D == C (accumulating)
__device__ __forceinline__ void mma1688(float* c, const uint32_t* a, const uint32_t* b) {
    asm volatile(
        "mma.sync.aligned.m16n8k8.row.col.f32.tf32.tf32.f32 "
        "{%0,%1,%2,%3}, {%4,%5,%6,%7}, {%8,%9}, {%0,%1,%2,%3};"
        : "+f"(c[0]), "+f"(c[1]), "+f"(c[2]), "+f"(c[3])
        : "r"(a[0]), "r"(a[1]), "r"(a[2]), "r"(a[3]), "r"(b[0]), "r"(b[1]));
}

struct Epi {
    float L[BLK_M * 65];
    float m1[BLK_M], rs[BLK_M];
    int   i1[BLK_M];
    int   flag;
    float rP[4][NEXP], rC[4][NEXP], red[NEXP];
};

__global__ void __launch_bounds__(NT, 1)
router_kernel(const float* __restrict__ x, const float* __restrict__ W,
              float* __restrict__ out)
{
    extern __shared__ __align__(16) float smf[];
    const int tid  = threadIdx.x;
    const int wid  = tid >> 5;
    const int lane = tid & 31;
    const int blk  = blockIdx.x;

    // ---- staging map: 6 x float4 per thread per chunk ----
    const float* sg[6];
    int sdst[6];                       // float offset within a stage
#pragma unroll
    for (int q = 0; q < 6; q++) {
        int f = q * NT + tid;          // 0..1535
        if (f < 1024) {                // x: 128 rows x 8 float4
            int row = f >> 3, c4 = f & 7;
            sg[q]   = x + (size_t)blk * BLK_M * DDIM + (size_t)row * DDIM + c4 * 4;
            sdst[q] = row * PITCH + c4 * 4;          // into A_HI/A_LO
        } else {                       // W: 64 rows x 8 float4
            int g = f - 1024, row = g >> 3, c4 = g & 7;
            sg[q]   = W + (size_t)row * DDIM + c4 * 4;
            sdst[q] = B_HI + row * PITCH + c4 * 4;   // B_LO = +NEXP*PITCH
        }
    }

    float4 pf[6];
#pragma unroll
    for (int q = 0; q < 6; q++) pf[q] = *(const float4*)sg[q];

    // ---- warp tile: warp_m in 0..3 (32 tokens), warp_n in 0..1 (32 experts) ----
    const int m0 = (wid >> 1) * 32;
    const int n0 = (wid & 1) * 32;
    const int g  = lane >> 2;          // groupID 0..7
    const int tg = lane & 3;           // thread-in-group 0..3

    float acc[2][4][4];
#pragma unroll
    for (int mt = 0; mt < 2; mt++)
#pragma unroll
        for (int nt = 0; nt < 4; nt++)
#pragma unroll
            for (int r = 0; r < 4; r++) acc[mt][nt][r] = 0.0f;

    for (int c = 0; c < NCH; c++) {
        float* st = smf + (c & 1) * STG_F;
        // split + store staged chunk (hi to *_HI, residual lo to *_LO)
#pragma unroll
        for (int q = 0; q < 6; q++) {
            float4 v = pf[q], h, l;
            h.x = tf32_rn(v.x); l.x = tf32_rn(v.x - h.x);
            h.y = tf32_rn(v.y); l.y = tf32_rn(v.y - h.y);
            h.z = tf32_rn(v.z); l.z = tf32_rn(v.z - h.z);
            h.w = tf32_rn(v.w); l.w = tf32_rn(v.w - h.w);
            int lo_off = (q < 4) ? (A_LO - A_HI) : (B_LO - B_HI);
            *(float4*)(st + sdst[q])          = h;
            *(float4*)(st + sdst[q] + lo_off) = l;
        }
        // prefetch next chunk while MMAs run
        if (c + 1 < NCH) {
            int off = (c + 1) * KCH;
#pragma unroll
            for (int q = 0; q < 6; q++) pf[q] = *(const float4*)(sg[q] + off);
        }
        __syncthreads();   // staged data visible; also orders MMA(c-1) vs this STS

        const uint32_t* su = (const uint32_t*)st;
#pragma unroll
        for (int ks = 0; ks < 4; ks++) {
            const int k0 = ks * 8;
            uint32_t ah[2][4], al[2][4];
#pragma unroll
            for (int mt = 0; mt < 2; mt++) {
                int r = (m0 + mt * 16 + g) * PITCH + k0 + tg;
                ah[mt][0] = su[A_HI + r];
                ah[mt][1] = su[A_HI + r + 8 * PITCH];
                ah[mt][2] = su[A_HI + r + 4];
                ah[mt][3] = su[A_HI + r + 8 * PITCH + 4];
                al[mt][0] = su[A_LO + r];
                al[mt][1] = su[A_LO + r + 8 * PITCH];
                al[mt][2] = su[A_LO + r + 4];
                al[mt][3] = su[A_LO + r + 8 * PITCH + 4];
            }
            uint32_t bh[4][2], bl[4][2];
#pragma unroll
            for (int nt = 0; nt < 4; nt++) {
                int r = (n0 + nt * 8 + g) * PITCH + k0 + tg;
                bh[nt][0] = su[B_HI + r];
                bh[nt][1] = su[B_HI + r + 4];
                bl[nt][0] = su[B_LO + r];
                bl[nt][1] = su[B_LO + r + 4];
            }
#pragma unroll
            for (int mt = 0; mt < 2; mt++)
#pragma unroll
                for (int nt = 0; nt < 4; nt++) {
                    mma1688(acc[mt][nt], al[mt], bh[nt]);   // lo*hi
                    mma1688(acc[mt][nt], ah[mt], bl[nt]);   // hi*lo
                    mma1688(acc[mt][nt], ah[mt], bh[nt]);   // hi*hi
                }
        }
    }
    __syncthreads();       // all smem reads done before epilogue overlay

    Epi* ep = (Epi*)smf;
    // ---- spill logits: D frag (mt,nt): rows m0+mt*16+g(+8), cols n0+nt*8+2tg(+1)
#pragma unroll
    for (int mt = 0; mt < 2; mt++) {
        int r = m0 + mt * 16 + g;
#pragma unroll
        for (int nt = 0; nt < 4; nt++) {
            int col = n0 + nt * 8 + 2 * tg;
            ep->L[r * 65 + col]           = acc[mt][nt][0];
            ep->L[r * 65 + col + 1]       = acc[mt][nt][1];
            ep->L[(r + 8) * 65 + col]     = acc[mt][nt][2];
            ep->L[(r + 8) * 65 + col + 1] = acc[mt][nt][3];
        }
    }
    __syncthreads();

    // one thread per token: top-2 (strict >, lowest index on ties, like lax.top_k)
    if (tid < BLK_M) {
        const float* row = ep->L + tid * 65;
        float m1 = -3.402823466e38f, m2 = -3.402823466e38f;
        int i1 = 0, i2 = 0;
#pragma unroll
        for (int e = 0; e < NEXP; e++) {
            float v = row[e];
            if (v > m1)      { m2 = m1; i2 = i1; m1 = v; i1 = e; }
            else if (v > m2) { m2 = v; i2 = e; }
        }
        float s = 0.0f;
#pragma unroll
        for (int e = 0; e < NEXP; e++) s += __expf(row[e] - m1);

        ep->m1[tid] = m1;
        ep->rs[tid] = 1.0f / s;
        ep->i1[tid] = i1;

        int gg = blk * BLK_M + tid;
        float q   = __expf(m2 - m1);
        float inv = 1.0f / (1.0f + q);
        out[2 * gg]               = (float)i1;   // top_k_indices
        out[2 * gg + 1]           = (float)i2;
        out[2 * TOK + 2 * gg]     = inv;         // top_k_weights
        out[2 * TOK + 2 * gg + 1] = q * inv;
    }
    __syncthreads();

    // one thread per expert: deterministic per-block prob-sum / top-1 count
    if (tid < NEXP) {
        float ps = 0.0f, cs = 0.0f;
#pragma unroll 8
        for (int t = 0; t < BLK_M; t++) {
            ps += __expf(ep->L[t * 65 + tid] - ep->m1[t]) * ep->rs[t];
            cs += (ep->i1[t] == tid) ? 1.0f : 0.0f;
        }
        g_pprob[blk * NEXP + tid] = ps;
        g_pcnt [blk * NEXP + tid] = cs;
    }
    __syncthreads();

    // ---- fused aux loss: last-arriving block folds all partials ----
    if (tid == 0) {
        __threadfence();
        unsigned old = atomicAdd(&g_arrival, 1u);
        ep->flag = (old == NBLK - 1) ? 1 : 0;
    }
    __syncthreads();
    if (ep->flag) {
        __threadfence();
        int e = tid & 63, h = tid >> 6;       // 4 parts x 32 blocks
        float sp = 0.0f, sc = 0.0f;
        int b0 = h * (NBLK / 4);
#pragma unroll 8
        for (int b = b0; b < b0 + NBLK / 4; b++) {
            sp += g_pprob[b * NEXP + e];
            sc += g_pcnt [b * NEXP + e];
        }
        ep->rP[h][e] = sp;
        ep->rC[h][e] = sc;
        __syncthreads();
        if (tid < NEXP) {
            float P = ep->rP[0][tid] + ep->rP[1][tid] + ep->rP[2][tid] + ep->rP[3][tid];
            float C = ep->rC[0][tid] + ep->rC[1][tid] + ep->rC[2][tid] + ep->rC[3][tid];
            ep->red[tid] = (C * (1.0f / TOK)) * (P * (1.0f / TOK));
        }
        __syncthreads();
        if (tid == 0) {
            float s = 0.0f;
            for (int k = 0; k < NEXP; k++) s += ep->red[k];
            out[4 * TOK] = (float)NEXP * s * 0.01f;  // E * sum * aux_w
            g_arrival = 0;                            // reset for next graph replay
        }
    }
}

extern "C" void kernel_launch(void* const* d_in, const int* in_sizes, int n_in,
                              void* d_out, int out_size)
{
    const float* x = (const float*)d_in[0];
    const float* W = (const float*)d_in[1];
    if (n_in >= 2 && in_sizes[0] == NEXP * DDIM && in_sizes[1] == TOK * DDIM) {
        const float* t = x; x = W; W = t;
    }
    cudaFuncSetAttribute(router_kernel,
                         cudaFuncAttributeMaxDynamicSharedMemorySize, SMEM_TOTAL);
    router_kernel<<<NBLK, NT, SMEM_TOTAL>>>(x, W, (float*)d_out);
}